// round 1
// baseline (speedup 1.0000x reference)
#include <cuda_runtime.h>
#include <cstdint>
#include <math_constants.h>

// Causal attention: B=4, H=16, S=2048, D=64, fp32 in/out.
// Flash-attention-2 style, TF32 mma.sync (m16n8k8), online softmax in exp2 domain.
//
// Tiling: one CTA = one (b,h) head x 64 query rows. 4 warps, each warp owns 16
// query rows. Iterate over 64-key blocks up to the causal diagonal.
// Q fragments live in registers across the whole KV loop. P staged through
// smem (per-warp rows -> only __syncwarp needed between P-write and P-read).
// Smem row stride = 72 words: makes Q-A/K-B/V-B fragment loads and P stores
// all bank-conflict-free (banks (8g+tig), (8tig+g), (8g+2tig) mod 32).

#define BATCH 4
#define HEADS 16
#define SEQ   2048
#define DIM   64

constexpr int BR  = 64;   // query rows per CTA
constexpr int BC  = 64;   // key cols per tile
constexpr int PAD = 72;   // smem row stride in 32-bit words
constexpr int NQBLK = SEQ / BR;   // 32
constexpr int NKT = DIM / 8;      // 8 k-steps of 8
constexpr int NNT = BC / 8;       // 8 n-tiles of 8

__device__ __forceinline__ unsigned f2tf32(float f) {
    unsigned u;
    asm("cvt.rna.tf32.f32 %0, %1;" : "=r"(u) : "f"(f));
    return u;
}

__device__ __forceinline__ void mma_tf32(float c[4],
                                         unsigned a0, unsigned a1, unsigned a2, unsigned a3,
                                         unsigned b0, unsigned b1) {
    asm volatile(
        "mma.sync.aligned.m16n8k8.row.col.f32.tf32.tf32.f32 "
        "{%0,%1,%2,%3}, {%4,%5,%6,%7}, {%8,%9}, {%0,%1,%2,%3};"
        : "+f"(c[0]), "+f"(c[1]), "+f"(c[2]), "+f"(c[3])
        : "r"(a0), "r"(a1), "r"(a2), "r"(a3), "r"(b0), "r"(b1));
}

__global__ void __launch_bounds__(128)
fa_tf32_kernel(const float* __restrict__ q,
               const float* __restrict__ k,
               const float* __restrict__ v,
               float* __restrict__ out) {
    extern __shared__ unsigned sm[];
    unsigned* sK = sm;                 // 64 x 72 words
    unsigned* sV = sm + BC * PAD;      // 64 x 72 words
    unsigned* sP = sm + 2 * BC * PAD;  // 64 x 72 words; also Q staging

    const int bh   = blockIdx.x;
    const int qblk = (NQBLK - 1) - blockIdx.y;  // heavy (long) blocks launch first
    const int tid  = threadIdx.x;
    const int w    = tid >> 5;
    const int lane = tid & 31;
    const int g    = lane >> 2;   // group id 0..7
    const int tig  = lane & 3;    // thread-in-group 0..3

    // fold softmax scale (1/sqrt(D)) and log2(e) into Q so we can use exp2f
    const float QSCALE = 0.125f * 1.4426950408889634f;

    const size_t qbase  = ((size_t)bh * SEQ + (size_t)qblk * BR) * DIM;
    const size_t kvhead = (size_t)bh * SEQ * DIM;

    // ---- stage Q (scaled, tf32-rounded) into sP, cooperatively ----
    #pragma unroll
    for (int i = 0; i < 8; i++) {
        int idx = i * 128 + tid;          // 1024 float4s total
        int row = idx >> 4;
        int c4  = (idx & 15) << 2;
        float4 qv = *reinterpret_cast<const float4*>(q + qbase + row * DIM + c4);
        unsigned* dst = sP + row * PAD + c4;
        dst[0] = f2tf32(qv.x * QSCALE);
        dst[1] = f2tf32(qv.y * QSCALE);
        dst[2] = f2tf32(qv.z * QSCALE);
        dst[3] = f2tf32(qv.w * QSCALE);
    }
    __syncthreads();

    // ---- pull Q fragments into registers (reused across all key blocks) ----
    const int r0 = w * 16 + g;       // this thread's first q row (local)
    unsigned qa[NKT][4];
    #pragma unroll
    for (int kt = 0; kt < NKT; kt++) {
        qa[kt][0] = sP[r0 * PAD + kt * 8 + tig];
        qa[kt][1] = sP[(r0 + 8) * PAD + kt * 8 + tig];
        qa[kt][2] = sP[r0 * PAD + kt * 8 + tig + 4];
        qa[kt][3] = sP[(r0 + 8) * PAD + kt * 8 + tig + 4];
    }
    // sP rows of warp w are only ever touched by warp w from here on.

    float o[NNT][4];
    #pragma unroll
    for (int nt = 0; nt < NNT; nt++) {
        o[nt][0] = 0.f; o[nt][1] = 0.f; o[nt][2] = 0.f; o[nt][3] = 0.f;
    }
    float m0 = -CUDART_INF_F, m1 = -CUDART_INF_F;
    float l0 = 0.f, l1 = 0.f;

    for (int jb = 0; jb <= qblk; jb++) {
        // ---- load K,V tiles (tf32-rounded) ----
        const float* kg = k + kvhead + (size_t)jb * BC * DIM;
        const float* vg = v + kvhead + (size_t)jb * BC * DIM;
        #pragma unroll
        for (int i = 0; i < 8; i++) {
            int idx = i * 128 + tid;
            int row = idx >> 4;
            int c4  = (idx & 15) << 2;
            float4 kv4 = *reinterpret_cast<const float4*>(kg + row * DIM + c4);
            unsigned* dk = sK + row * PAD + c4;
            dk[0] = f2tf32(kv4.x); dk[1] = f2tf32(kv4.y);
            dk[2] = f2tf32(kv4.z); dk[3] = f2tf32(kv4.w);
            float4 vv4 = *reinterpret_cast<const float4*>(vg + row * DIM + c4);
            unsigned* dv = sV + row * PAD + c4;
            dv[0] = f2tf32(vv4.x); dv[1] = f2tf32(vv4.y);
            dv[2] = f2tf32(vv4.z); dv[3] = f2tf32(vv4.w);
        }
        __syncthreads();

        // ---- S = Q @ K^T  (16 x 64 per warp) ----
        float s[NNT][4];
        #pragma unroll
        for (int nt = 0; nt < NNT; nt++) {
            s[nt][0] = 0.f; s[nt][1] = 0.f; s[nt][2] = 0.f; s[nt][3] = 0.f;
        }
        #pragma unroll
        for (int kt = 0; kt < NKT; kt++) {
            #pragma unroll
            for (int nt = 0; nt < NNT; nt++) {
                unsigned b0 = sK[(nt * 8 + g) * PAD + kt * 8 + tig];
                unsigned b1 = sK[(nt * 8 + g) * PAD + kt * 8 + tig + 4];
                mma_tf32(s[nt], qa[kt][0], qa[kt][1], qa[kt][2], qa[kt][3], b0, b1);
            }
        }

        // ---- causal mask (diagonal block only) ----
        if (jb == qblk) {
            #pragma unroll
            for (int nt = 0; nt < NNT; nt++) {
                int c0 = nt * 8 + 2 * tig;
                int c1 = c0 + 1;
                if (c0 > r0)     s[nt][0] = -CUDART_INF_F;
                if (c1 > r0)     s[nt][1] = -CUDART_INF_F;
                if (c0 > r0 + 8) s[nt][2] = -CUDART_INF_F;
                if (c1 > r0 + 8) s[nt][3] = -CUDART_INF_F;
            }
        }

        // ---- online softmax (exp2 domain; scale folded into Q) ----
        float mx0 = -CUDART_INF_F, mx1 = -CUDART_INF_F;
        #pragma unroll
        for (int nt = 0; nt < NNT; nt++) {
            mx0 = fmaxf(mx0, fmaxf(s[nt][0], s[nt][1]));
            mx1 = fmaxf(mx1, fmaxf(s[nt][2], s[nt][3]));
        }
        mx0 = fmaxf(mx0, __shfl_xor_sync(0xffffffffu, mx0, 1));
        mx0 = fmaxf(mx0, __shfl_xor_sync(0xffffffffu, mx0, 2));
        mx1 = fmaxf(mx1, __shfl_xor_sync(0xffffffffu, mx1, 1));
        mx1 = fmaxf(mx1, __shfl_xor_sync(0xffffffffu, mx1, 2));

        float mn0 = fmaxf(m0, mx0);
        float mn1 = fmaxf(m1, mx1);
        float a0 = exp2f(m0 - mn0);
        float a1 = exp2f(m1 - mn1);
        m0 = mn0; m1 = mn1;

        float rs0 = 0.f, rs1 = 0.f;
        #pragma unroll
        for (int nt = 0; nt < NNT; nt++) {
            s[nt][0] = exp2f(s[nt][0] - mn0);
            s[nt][1] = exp2f(s[nt][1] - mn0);
            s[nt][2] = exp2f(s[nt][2] - mn1);
            s[nt][3] = exp2f(s[nt][3] - mn1);
            rs0 += s[nt][0] + s[nt][1];
            rs1 += s[nt][2] + s[nt][3];
        }
        rs0 += __shfl_xor_sync(0xffffffffu, rs0, 1);
        rs0 += __shfl_xor_sync(0xffffffffu, rs0, 2);
        rs1 += __shfl_xor_sync(0xffffffffu, rs1, 1);
        rs1 += __shfl_xor_sync(0xffffffffu, rs1, 2);
        l0 = l0 * a0 + rs0;
        l1 = l1 * a1 + rs1;

        #pragma unroll
        for (int nt = 0; nt < NNT; nt++) {
            o[nt][0] *= a0; o[nt][1] *= a0;
            o[nt][2] *= a1; o[nt][3] *= a1;
        }

        // ---- write P (tf32-rounded) to smem; per-warp rows ----
        #pragma unroll
        for (int nt = 0; nt < NNT; nt++) {
            sP[r0 * PAD + nt * 8 + 2 * tig]           = f2tf32(s[nt][0]);
            sP[r0 * PAD + nt * 8 + 2 * tig + 1]       = f2tf32(s[nt][1]);
            sP[(r0 + 8) * PAD + nt * 8 + 2 * tig]     = f2tf32(s[nt][2]);
            sP[(r0 + 8) * PAD + nt * 8 + 2 * tig + 1] = f2tf32(s[nt][3]);
        }
        __syncwarp();

        // ---- O += P @ V ----
        #pragma unroll
        for (int kt = 0; kt < NKT; kt++) {
            unsigned pa0 = sP[r0 * PAD + kt * 8 + tig];
            unsigned pa1 = sP[(r0 + 8) * PAD + kt * 8 + tig];
            unsigned pa2 = sP[r0 * PAD + kt * 8 + tig + 4];
            unsigned pa3 = sP[(r0 + 8) * PAD + kt * 8 + tig + 4];
            #pragma unroll
            for (int nt = 0; nt < NNT; nt++) {
                unsigned b0 = sV[(kt * 8 + tig) * PAD + nt * 8 + g];
                unsigned b1 = sV[(kt * 8 + tig + 4) * PAD + nt * 8 + g];
                mma_tf32(o[nt], pa0, pa1, pa2, pa3, b0, b1);
            }
        }
        __syncthreads();  // all warps done with sK/sV before next load
    }

    // ---- epilogue: normalize and write ----
    const float i0 = 1.f / l0;
    const float i1 = 1.f / l1;
    float* og = out + qbase;
    #pragma unroll
    for (int nt = 0; nt < NNT; nt++) {
        float2 v0 = make_float2(o[nt][0] * i0, o[nt][1] * i0);
        float2 v1 = make_float2(o[nt][2] * i1, o[nt][3] * i1);
        *reinterpret_cast<float2*>(og + r0 * DIM + nt * 8 + 2 * tig)       = v0;
        *reinterpret_cast<float2*>(og + (r0 + 8) * DIM + nt * 8 + 2 * tig) = v1;
    }
}

extern "C" void kernel_launch(void* const* d_in, const int* in_sizes, int n_in,
                              void* d_out, int out_size) {
    (void)in_sizes; (void)n_in; (void)out_size;
    const float* q = (const float*)d_in[0];
    const float* k = (const float*)d_in[1];
    const float* v = (const float*)d_in[2];
    // d_in[3] is the causal mask; causality is computed analytically.
    float* out = (float*)d_out;

    const int smem_bytes = 3 * BC * PAD * 4;  // 55296
    cudaFuncSetAttribute(fa_tf32_kernel,
                         cudaFuncAttributeMaxDynamicSharedMemorySize, smem_bytes);

    dim3 grid(BATCH * HEADS, NQBLK);  // x = head, y = reversed q-block
    dim3 block(128);
    fa_tf32_kernel<<<grid, block, smem_bytes>>>(q, k, v, out);
}

// round 3
// speedup vs baseline: 1.2499x; 1.2499x over previous
#include <cuda_runtime.h>
#include <cstdint>
#include <math_constants.h>

// Causal attention B=4,H=16,S=2048,D=64 fp32. FA2 + TF32 mma.sync.
// R2: 4 warps x 32 q-rows each (two m16 blocks) -> K/V fragment LDS bytes
// halved per MMA. K/Q column-permuted per 8-group [0,4,1,5,2,6,3,7] so
// B/A fragment pairs (k, k+4) load as one LDS.64; P stores are STS.64.

#define BATCH 4
#define HEADS 16
#define SEQ   2048
#define DIM   64

constexpr int BR  = 128;  // query rows per CTA (4 warps x 32)
constexpr int BC  = 64;   // key cols per tile
constexpr int PAD = 72;   // smem row stride (words)
constexpr int NQBLK = SEQ / BR;   // 16
constexpr int NKT = DIM / 8;      // 8
constexpr int NNT = BC / 8;       // 8

__device__ __forceinline__ unsigned f2tf32(float f) {
    unsigned u;
    asm("cvt.rna.tf32.f32 %0, %1;" : "=r"(u) : "f"(f));
    return u;
}
__device__ __forceinline__ float ex2(float x) {
    float y;
    asm("ex2.approx.ftz.f32 %0, %1;" : "=f"(y) : "f"(x));
    return y;
}
__device__ __forceinline__ void mma_tf32(float c[4],
                                         unsigned a0, unsigned a1, unsigned a2, unsigned a3,
                                         unsigned b0, unsigned b1) {
    asm volatile(
        "mma.sync.aligned.m16n8k8.row.col.f32.tf32.tf32.f32 "
        "{%0,%1,%2,%3}, {%4,%5,%6,%7}, {%8,%9}, {%0,%1,%2,%3};"
        : "+f"(c[0]), "+f"(c[1]), "+f"(c[2]), "+f"(c[3])
        : "r"(a0), "r"(a1), "r"(a2), "r"(a3), "r"(b0), "r"(b1));
}

__global__ void __launch_bounds__(128, 2)
fa_tf32_kernel(const float* __restrict__ q,
               const float* __restrict__ k,
               const float* __restrict__ v,
               float* __restrict__ out) {
    extern __shared__ unsigned sm[];
    unsigned* sK = sm;                  // 64 x 72 (permuted cols)
    unsigned* sV = sm + BC * PAD;       // 64 x 72 (straight)
    unsigned* sP = sm + 2 * BC * PAD;   // 128 x 72 (straight; Q staging permuted)

    const int bh   = blockIdx.x;
    const int qblk = (NQBLK - 1) - blockIdx.y;   // heavy blocks first
    const int tid  = threadIdx.x;
    const int w    = tid >> 5;
    const int lane = tid & 31;
    const int g    = lane >> 2;
    const int tig  = lane & 3;
    const int r0   = w * 32 + g;        // warp owns local rows [w*32, w*32+31]

    const float QSCALE = 0.125f * 1.4426950408889634f;  // 1/sqrt(64) * log2(e)

    const size_t qbase  = ((size_t)bh * SEQ + (size_t)qblk * BR) * DIM;
    const size_t kvhead = (size_t)bh * SEQ * DIM;

    // ---- stage Q, scaled + tf32, column-permuted per 8-group ----
    #pragma unroll
    for (int i = 0; i < 16; i++) {
        int idx = i * 128 + tid;              // 2048 quads
        int row = idx >> 4;
        int c4  = (idx & 15) << 2;
        float4 qv = *reinterpret_cast<const float4*>(q + qbase + row * DIM + c4);
        int pbase = (c4 & ~7) | ((c4 & 4) >> 2);
        unsigned* dst = sP + row * PAD + pbase;
        dst[0] = f2tf32(qv.x * QSCALE);
        dst[2] = f2tf32(qv.y * QSCALE);
        dst[4] = f2tf32(qv.z * QSCALE);
        dst[6] = f2tf32(qv.w * QSCALE);
    }
    __syncthreads();

    // ---- Q fragments for both m16 blocks (u=0,1), kept in registers ----
    unsigned qa[2][NKT][4];
    #pragma unroll
    for (int u = 0; u < 2; u++) {
        #pragma unroll
        for (int kt = 0; kt < NKT; kt++) {
            uint2 a02 = *reinterpret_cast<uint2*>(sP + (r0 + 16 * u) * PAD + kt * 8 + 2 * tig);
            uint2 a13 = *reinterpret_cast<uint2*>(sP + (r0 + 16 * u + 8) * PAD + kt * 8 + 2 * tig);
            qa[u][kt][0] = a02.x; qa[u][kt][1] = a13.x;
            qa[u][kt][2] = a02.y; qa[u][kt][3] = a13.y;
        }
    }

    float o[2][NNT][4];
    #pragma unroll
    for (int u = 0; u < 2; u++)
        #pragma unroll
        for (int nt = 0; nt < NNT; nt++) {
            o[u][nt][0] = 0.f; o[u][nt][1] = 0.f; o[u][nt][2] = 0.f; o[u][nt][3] = 0.f;
        }
    float m[2][2], l[2][2];
    m[0][0] = m[0][1] = m[1][0] = m[1][1] = -CUDART_INF_F;
    l[0][0] = l[0][1] = l[1][0] = l[1][1] = 0.f;

    const int njb = 2 * qblk + 2;
    for (int jb = 0; jb < njb; jb++) {
        // ---- stage K (permuted) and V (straight), tf32 ----
        const float* kg = k + kvhead + (size_t)jb * BC * DIM;
        const float* vg = v + kvhead + (size_t)jb * BC * DIM;
        #pragma unroll
        for (int i = 0; i < 8; i++) {
            int idx = i * 128 + tid;          // 1024 quads
            int row = idx >> 4;
            int c4  = (idx & 15) << 2;
            float4 k4 = *reinterpret_cast<const float4*>(kg + row * DIM + c4);
            int pbase = (c4 & ~7) | ((c4 & 4) >> 2);
            unsigned* dk = sK + row * PAD + pbase;
            dk[0] = f2tf32(k4.x); dk[2] = f2tf32(k4.y);
            dk[4] = f2tf32(k4.z); dk[6] = f2tf32(k4.w);
            float4 v4 = *reinterpret_cast<const float4*>(vg + row * DIM + c4);
            unsigned* dv = sV + row * PAD + c4;
            dv[0] = f2tf32(v4.x); dv[1] = f2tf32(v4.y);
            dv[2] = f2tf32(v4.z); dv[3] = f2tf32(v4.w);
        }
        __syncthreads();

        // ---- S = Q K^T : each K fragment pair feeds 2 MMAs ----
        float s[2][NNT][4];
        #pragma unroll
        for (int u = 0; u < 2; u++)
            #pragma unroll
            for (int nt = 0; nt < NNT; nt++) {
                s[u][nt][0] = 0.f; s[u][nt][1] = 0.f; s[u][nt][2] = 0.f; s[u][nt][3] = 0.f;
            }
        #pragma unroll
        for (int kt = 0; kt < NKT; kt++) {
            #pragma unroll
            for (int nt = 0; nt < NNT; nt++) {
                uint2 kb = *reinterpret_cast<uint2*>(sK + (nt * 8 + g) * PAD + kt * 8 + 2 * tig);
                mma_tf32(s[0][nt], qa[0][kt][0], qa[0][kt][1], qa[0][kt][2], qa[0][kt][3], kb.x, kb.y);
                mma_tf32(s[1][nt], qa[1][kt][0], qa[1][kt][1], qa[1][kt][2], qa[1][kt][3], kb.x, kb.y);
            }
        }

        // ---- causal mask (only blocks that straddle the diagonal) ----
        if (jb >= 2 * qblk) {
            const int colb = jb * BC;
            #pragma unroll
            for (int u = 0; u < 2; u++) {
                const int rowg = qblk * BR + r0 + 16 * u;
                #pragma unroll
                for (int nt = 0; nt < NNT; nt++) {
                    int c0 = colb + nt * 8 + 2 * tig;
                    int c1 = c0 + 1;
                    if (c0 > rowg)     s[u][nt][0] = -CUDART_INF_F;
                    if (c1 > rowg)     s[u][nt][1] = -CUDART_INF_F;
                    if (c0 > rowg + 8) s[u][nt][2] = -CUDART_INF_F;
                    if (c1 > rowg + 8) s[u][nt][3] = -CUDART_INF_F;
                }
            }
        }

        // ---- online softmax per m16 block ----
        #pragma unroll
        for (int u = 0; u < 2; u++) {
            float mx0 = -CUDART_INF_F, mx1 = -CUDART_INF_F;
            #pragma unroll
            for (int nt = 0; nt < NNT; nt++) {
                mx0 = fmaxf(mx0, fmaxf(s[u][nt][0], s[u][nt][1]));
                mx1 = fmaxf(mx1, fmaxf(s[u][nt][2], s[u][nt][3]));
            }
            mx0 = fmaxf(mx0, __shfl_xor_sync(0xffffffffu, mx0, 1));
            mx0 = fmaxf(mx0, __shfl_xor_sync(0xffffffffu, mx0, 2));
            mx1 = fmaxf(mx1, __shfl_xor_sync(0xffffffffu, mx1, 1));
            mx1 = fmaxf(mx1, __shfl_xor_sync(0xffffffffu, mx1, 2));

            float mn0 = fmaxf(m[u][0], mx0);
            float mn1 = fmaxf(m[u][1], mx1);
            float a0 = ex2(m[u][0] - mn0);
            float a1 = ex2(m[u][1] - mn1);
            m[u][0] = mn0; m[u][1] = mn1;

            float rs0 = 0.f, rs1 = 0.f;
            #pragma unroll
            for (int nt = 0; nt < NNT; nt++) {
                s[u][nt][0] = ex2(s[u][nt][0] - mn0);
                s[u][nt][1] = ex2(s[u][nt][1] - mn0);
                s[u][nt][2] = ex2(s[u][nt][2] - mn1);
                s[u][nt][3] = ex2(s[u][nt][3] - mn1);
                rs0 += s[u][nt][0] + s[u][nt][1];
                rs1 += s[u][nt][2] + s[u][nt][3];
            }
            rs0 += __shfl_xor_sync(0xffffffffu, rs0, 1);
            rs0 += __shfl_xor_sync(0xffffffffu, rs0, 2);
            rs1 += __shfl_xor_sync(0xffffffffu, rs1, 1);
            rs1 += __shfl_xor_sync(0xffffffffu, rs1, 2);
            l[u][0] = l[u][0] * a0 + rs0;
            l[u][1] = l[u][1] * a1 + rs1;

            #pragma unroll
            for (int nt = 0; nt < NNT; nt++) {
                o[u][nt][0] *= a0; o[u][nt][1] *= a0;
                o[u][nt][2] *= a1; o[u][nt][3] *= a1;
            }

            // P store: cols (2tig, 2tig+1) adjacent -> STS.64, conflict-free
            #pragma unroll
            for (int nt = 0; nt < NNT; nt++) {
                uint2 w0, w1;
                w0.x = f2tf32(s[u][nt][0]); w0.y = f2tf32(s[u][nt][1]);
                w1.x = f2tf32(s[u][nt][2]); w1.y = f2tf32(s[u][nt][3]);
                *reinterpret_cast<uint2*>(sP + (r0 + 16 * u) * PAD + nt * 8 + 2 * tig)     = w0;
                *reinterpret_cast<uint2*>(sP + (r0 + 16 * u + 8) * PAD + nt * 8 + 2 * tig) = w1;
            }
        }
        __syncwarp();

        // ---- O += P V : each V fragment pair feeds 2 MMAs ----
        #pragma unroll
        for (int kt = 0; kt < NKT; kt++) {
            unsigned pa[2][4];
            #pragma unroll
            for (int u = 0; u < 2; u++) {
                pa[u][0] = sP[(r0 + 16 * u) * PAD + kt * 8 + tig];
                pa[u][1] = sP[(r0 + 16 * u + 8) * PAD + kt * 8 + tig];
                pa[u][2] = sP[(r0 + 16 * u) * PAD + kt * 8 + tig + 4];
                pa[u][3] = sP[(r0 + 16 * u + 8) * PAD + kt * 8 + tig + 4];
            }
            #pragma unroll
            for (int nt = 0; nt < NNT; nt++) {
                unsigned vb0 = sV[(kt * 8 + tig) * PAD + nt * 8 + g];
                unsigned vb1 = sV[(kt * 8 + tig + 4) * PAD + nt * 8 + g];
                mma_tf32(o[0][nt], pa[0][0], pa[0][1], pa[0][2], pa[0][3], vb0, vb1);
                mma_tf32(o[1][nt], pa[1][0], pa[1][1], pa[1][2], pa[1][3], vb0, vb1);
            }
        }
        __syncthreads();   // protect sK/sV for next stage
    }

    // ---- epilogue ----
    float* og = out + qbase;
    #pragma unroll
    for (int u = 0; u < 2; u++) {
        const float i0 = 1.f / l[u][0];
        const float i1 = 1.f / l[u][1];
        #pragma unroll
        for (int nt = 0; nt < NNT; nt++) {
            float2 v0 = make_float2(o[u][nt][0] * i0, o[u][nt][1] * i0);
            float2 v1 = make_float2(o[u][nt][2] * i1, o[u][nt][3] * i1);
            *reinterpret_cast<float2*>(og + (r0 + 16 * u) * DIM + nt * 8 + 2 * tig)     = v0;
            *reinterpret_cast<float2*>(og + (r0 + 16 * u + 8) * DIM + nt * 8 + 2 * tig) = v1;
        }
    }
}

extern "C" void kernel_launch(void* const* d_in, const int* in_sizes, int n_in,
                              void* d_out, int out_size) {
    (void)in_sizes; (void)n_in; (void)out_size;
    const float* q = (const float*)d_in[0];
    const float* k = (const float*)d_in[1];
    const float* v = (const float*)d_in[2];
    float* out = (float*)d_out;

    const int smem_bytes = (2 * BC * PAD + BR * PAD) * 4;  // 73728
    cudaFuncSetAttribute(fa_tf32_kernel,
                         cudaFuncAttributeMaxDynamicSharedMemorySize, smem_bytes);

    dim3 grid(BATCH * HEADS, NQBLK);
    dim3 block(128);
    fa_tf32_kernel<<<grid, block, smem_bytes>>>(q, k, v, out);
}

// round 6
// speedup vs baseline: 1.4113x; 1.1291x over previous
#include <cuda_runtime.h>
#include <cuda_fp16.h>
#include <cstdint>
#include <math_constants.h>

// Causal attention B=4,H=16,S=2048,D=64 fp32. FA2.
// QK^T: TF32 mma m16n8k8 (K column-permuted, LDS.64 fragment pairs).
// PV:   FP16 mma m16n8k16; P packed in registers straight from the S
//       accumulator (layout match) -> NO P smem round-trip.
// V:    fp16 in smem, XOR-swizzled 16B units, loaded via ldmatrix.x4.trans.

#define BATCH 4
#define HEADS 16
#define SEQ   2048
#define DIM   64

constexpr int BR  = 128;  // query rows per CTA (4 warps x 32)
constexpr int BC  = 64;   // key cols per tile
constexpr int PAD = 72;   // fp32 smem row stride (words) for Q/K
constexpr int VPADH = 72; // V smem row stride in halves (144B, 16B-aligned)
constexpr int NQBLK = SEQ / BR;   // 16
constexpr int NKT = DIM / 8;      // 8
constexpr int NNT = BC / 8;       // 8

__device__ __forceinline__ unsigned f2tf32(float f) {
    unsigned u;
    asm("cvt.rna.tf32.f32 %0, %1;" : "=r"(u) : "f"(f));
    return u;
}
__device__ __forceinline__ float ex2(float x) {
    float y;
    asm("ex2.approx.ftz.f32 %0, %1;" : "=f"(y) : "f"(x));
    return y;
}
__device__ __forceinline__ unsigned packh2(float a, float b) {
    __half2 h = __floats2half2_rn(a, b);
    return *reinterpret_cast<unsigned*>(&h);
}
__device__ __forceinline__ void mma_tf32(float c[4],
                                         unsigned a0, unsigned a1, unsigned a2, unsigned a3,
                                         unsigned b0, unsigned b1) {
    asm volatile(
        "mma.sync.aligned.m16n8k8.row.col.f32.tf32.tf32.f32 "
        "{%0,%1,%2,%3}, {%4,%5,%6,%7}, {%8,%9}, {%0,%1,%2,%3};"
        : "+f"(c[0]), "+f"(c[1]), "+f"(c[2]), "+f"(c[3])
        : "r"(a0), "r"(a1), "r"(a2), "r"(a3), "r"(b0), "r"(b1));
}
__device__ __forceinline__ void mma_f16(float c[4],
                                        unsigned a0, unsigned a1, unsigned a2, unsigned a3,
                                        unsigned b0, unsigned b1) {
    asm volatile(
        "mma.sync.aligned.m16n8k16.row.col.f32.f16.f16.f32 "
        "{%0,%1,%2,%3}, {%4,%5,%6,%7}, {%8,%9}, {%0,%1,%2,%3};"
        : "+f"(c[0]), "+f"(c[1]), "+f"(c[2]), "+f"(c[3])
        : "r"(a0), "r"(a1), "r"(a2), "r"(a3), "r"(b0), "r"(b1));
}
__device__ __forceinline__ void ldsm4t(unsigned r[4], unsigned saddr) {
    asm volatile(
        "ldmatrix.sync.aligned.m8n8.x4.trans.shared.b16 {%0,%1,%2,%3}, [%4];"
        : "=r"(r[0]), "=r"(r[1]), "=r"(r[2]), "=r"(r[3]) : "r"(saddr));
}

__global__ void __launch_bounds__(128, 2)
fa_tf32_kernel(const float* __restrict__ q,
               const float* __restrict__ k,
               const float* __restrict__ v,
               float* __restrict__ out) {
    extern __shared__ unsigned sm[];
    // Region layout: Q staging (128x72 words) is read once into registers,
    // then the same region is reused for K (64x72 words) + V (fp16, 64x72 halves).
    unsigned* sQ = sm;                         // transient
    unsigned* sK = sm;                         // 64 x 72 words (permuted cols)
    __half*   sVh = reinterpret_cast<__half*>(sm + BC * PAD);  // 64 x 72 halves

    const int bh   = blockIdx.x;
    const int qblk = (NQBLK - 1) - blockIdx.y;
    const int tid  = threadIdx.x;
    const int w    = tid >> 5;
    const int lane = tid & 31;
    const int g    = lane >> 2;
    const int tig  = lane & 3;
    const int r0   = w * 32 + g;

    const float QSCALE = 0.125f * 1.4426950408889634f;

    const size_t qbase  = ((size_t)bh * SEQ + (size_t)qblk * BR) * DIM;
    const size_t kvhead = (size_t)bh * SEQ * DIM;

    // ---- stage Q (scaled, tf32, column-permuted per 8-group) ----
    #pragma unroll
    for (int i = 0; i < 16; i++) {
        int idx = i * 128 + tid;
        int row = idx >> 4;
        int c4  = (idx & 15) << 2;
        float4 qv = *reinterpret_cast<const float4*>(q + qbase + row * DIM + c4);
        int pbase = (c4 & ~7) | ((c4 & 4) >> 2);
        unsigned* dst = sQ + row * PAD + pbase;
        dst[0] = f2tf32(qv.x * QSCALE);
        dst[2] = f2tf32(qv.y * QSCALE);
        dst[4] = f2tf32(qv.z * QSCALE);
        dst[6] = f2tf32(qv.w * QSCALE);
    }
    __syncthreads();

    // ---- Q fragments into registers (persist across KV loop) ----
    unsigned qa[2][NKT][4];
    #pragma unroll
    for (int u = 0; u < 2; u++) {
        #pragma unroll
        for (int kt = 0; kt < NKT; kt++) {
            uint2 a02 = *reinterpret_cast<uint2*>(sQ + (r0 + 16 * u) * PAD + kt * 8 + 2 * tig);
            uint2 a13 = *reinterpret_cast<uint2*>(sQ + (r0 + 16 * u + 8) * PAD + kt * 8 + 2 * tig);
            qa[u][kt][0] = a02.x; qa[u][kt][1] = a13.x;
            qa[u][kt][2] = a02.y; qa[u][kt][3] = a13.y;
        }
    }
    __syncthreads();   // everyone done reading sQ; region becomes K/V

    float o[2][NNT][4];
    #pragma unroll
    for (int u = 0; u < 2; u++)
        #pragma unroll
        for (int nt = 0; nt < NNT; nt++) {
            o[u][nt][0] = 0.f; o[u][nt][1] = 0.f; o[u][nt][2] = 0.f; o[u][nt][3] = 0.f;
        }
    float m[2][2], l[2][2];
    m[0][0] = m[0][1] = m[1][0] = m[1][1] = -CUDART_INF_F;
    l[0][0] = l[0][1] = l[1][0] = l[1][1] = 0.f;

    // smem byte base of V for ldmatrix addressing
    const unsigned svh_base = (unsigned)__cvta_generic_to_shared(sVh);

    const int njb = 2 * qblk + 2;
    for (int jb = 0; jb < njb; jb++) {
        const float* kg = k + kvhead + (size_t)jb * BC * DIM;
        const float* vg = v + kvhead + (size_t)jb * BC * DIM;
        // ---- stage K (tf32, permuted) and V (fp16, XOR-swizzled units) ----
        #pragma unroll
        for (int i = 0; i < 8; i++) {
            int idx = i * 128 + tid;          // 1024 quads
            int row = idx >> 4;
            int c4  = (idx & 15) << 2;
            float4 k4 = *reinterpret_cast<const float4*>(kg + row * DIM + c4);
            int pbase = (c4 & ~7) | ((c4 & 4) >> 2);
            unsigned* dk = sK + row * PAD + pbase;
            dk[0] = f2tf32(k4.x); dk[2] = f2tf32(k4.y);
            dk[4] = f2tf32(k4.z); dk[6] = f2tf32(k4.w);
            float4 v4 = *reinterpret_cast<const float4*>(vg + row * DIM + c4);
            // logical 16B unit u16 = c4>>3, swizzled by row&7; sub-offset c4&4 halves
            int su = ((c4 >> 3) ^ (row & 7));
            unsigned hv0 = packh2(v4.x, v4.y);
            unsigned hv1 = packh2(v4.z, v4.w);
            *reinterpret_cast<uint2*>(sVh + row * VPADH + su * 8 + (c4 & 4)) =
                make_uint2(hv0, hv1);
        }
        __syncthreads();

        // ---- S = Q K^T (tf32) ----
        float s[2][NNT][4];
        #pragma unroll
        for (int u = 0; u < 2; u++)
            #pragma unroll
            for (int nt = 0; nt < NNT; nt++) {
                s[u][nt][0] = 0.f; s[u][nt][1] = 0.f; s[u][nt][2] = 0.f; s[u][nt][3] = 0.f;
            }
        #pragma unroll
        for (int kt = 0; kt < NKT; kt++) {
            #pragma unroll
            for (int nt = 0; nt < NNT; nt++) {
                uint2 kb = *reinterpret_cast<uint2*>(sK + (nt * 8 + g) * PAD + kt * 8 + 2 * tig);
                mma_tf32(s[0][nt], qa[0][kt][0], qa[0][kt][1], qa[0][kt][2], qa[0][kt][3], kb.x, kb.y);
                mma_tf32(s[1][nt], qa[1][kt][0], qa[1][kt][1], qa[1][kt][2], qa[1][kt][3], kb.x, kb.y);
            }
        }

        // ---- causal mask (diagonal-straddling blocks only) ----
        if (jb >= 2 * qblk) {
            const int colb = jb * BC;
            #pragma unroll
            for (int u = 0; u < 2; u++) {
                const int rowg = qblk * BR + r0 + 16 * u;
                #pragma unroll
                for (int nt = 0; nt < NNT; nt++) {
                    int c0 = colb + nt * 8 + 2 * tig;
                    int c1 = c0 + 1;
                    if (c0 > rowg)     s[u][nt][0] = -CUDART_INF_F;
                    if (c1 > rowg)     s[u][nt][1] = -CUDART_INF_F;
                    if (c0 > rowg + 8) s[u][nt][2] = -CUDART_INF_F;
                    if (c1 > rowg + 8) s[u][nt][3] = -CUDART_INF_F;
                }
            }
        }

        // ---- online softmax; pack P to fp16 A-fragments in registers ----
        unsigned pa[2][4][4];
        #pragma unroll
        for (int u = 0; u < 2; u++) {
            float mx0 = -CUDART_INF_F, mx1 = -CUDART_INF_F;
            #pragma unroll
            for (int nt = 0; nt < NNT; nt++) {
                mx0 = fmaxf(mx0, fmaxf(s[u][nt][0], s[u][nt][1]));
                mx1 = fmaxf(mx1, fmaxf(s[u][nt][2], s[u][nt][3]));
            }
            mx0 = fmaxf(mx0, __shfl_xor_sync(0xffffffffu, mx0, 1));
            mx0 = fmaxf(mx0, __shfl_xor_sync(0xffffffffu, mx0, 2));
            mx1 = fmaxf(mx1, __shfl_xor_sync(0xffffffffu, mx1, 1));
            mx1 = fmaxf(mx1, __shfl_xor_sync(0xffffffffu, mx1, 2));

            float mn0 = fmaxf(m[u][0], mx0);
            float mn1 = fmaxf(m[u][1], mx1);
            float a0 = ex2(m[u][0] - mn0);
            float a1 = ex2(m[u][1] - mn1);
            m[u][0] = mn0; m[u][1] = mn1;

            float rs0 = 0.f, rs1 = 0.f;
            #pragma unroll
            for (int nt = 0; nt < NNT; nt++) {
                s[u][nt][0] = ex2(s[u][nt][0] - mn0);
                s[u][nt][1] = ex2(s[u][nt][1] - mn0);
                s[u][nt][2] = ex2(s[u][nt][2] - mn1);
                s[u][nt][3] = ex2(s[u][nt][3] - mn1);
                rs0 += s[u][nt][0] + s[u][nt][1];
                rs1 += s[u][nt][2] + s[u][nt][3];
            }
            rs0 += __shfl_xor_sync(0xffffffffu, rs0, 1);
            rs0 += __shfl_xor_sync(0xffffffffu, rs0, 2);
            rs1 += __shfl_xor_sync(0xffffffffu, rs1, 1);
            rs1 += __shfl_xor_sync(0xffffffffu, rs1, 2);
            l[u][0] = l[u][0] * a0 + rs0;
            l[u][1] = l[u][1] * a1 + rs1;

            #pragma unroll
            for (int nt = 0; nt < NNT; nt++) {
                o[u][nt][0] *= a0; o[u][nt][1] *= a0;
                o[u][nt][2] *= a1; o[u][nt][3] *= a1;
            }

            // P -> fp16 A fragments, layout matches accumulator exactly
            #pragma unroll
            for (int t = 0; t < 4; t++) {
                pa[u][t][0] = packh2(s[u][2*t][0],   s[u][2*t][1]);
                pa[u][t][1] = packh2(s[u][2*t][2],   s[u][2*t][3]);
                pa[u][t][2] = packh2(s[u][2*t+1][0], s[u][2*t+1][1]);
                pa[u][t][3] = packh2(s[u][2*t+1][2], s[u][2*t+1][3]);
            }
        }

        // ---- O += P V (fp16 m16n8k16, V via ldmatrix.x4.trans) ----
        const int f   = lane & 15;
        const int h8  = lane >> 4;
        #pragma unroll
        for (int kt = 0; kt < 4; kt++) {
            const int krow = kt * 16 + f;
            #pragma unroll
            for (int nt2 = 0; nt2 < 4; nt2++) {
                const int unit = ((2 * nt2 + h8) ^ (krow & 7));
                unsigned saddr = svh_base + (unsigned)((krow * VPADH + unit * 8) * 2);
                unsigned vb[4];
                ldsm4t(vb, saddr);
                mma_f16(o[0][2*nt2],   pa[0][kt][0], pa[0][kt][1], pa[0][kt][2], pa[0][kt][3], vb[0], vb[1]);
                mma_f16(o[0][2*nt2+1], pa[0][kt][0], pa[0][kt][1], pa[0][kt][2], pa[0][kt][3], vb[2], vb[3]);
                mma_f16(o[1][2*nt2],   pa[1][kt][0], pa[1][kt][1], pa[1][kt][2], pa[1][kt][3], vb[0], vb[1]);
                mma_f16(o[1][2*nt2+1], pa[1][kt][0], pa[1][kt][1], pa[1][kt][2], pa[1][kt][3], vb[2], vb[3]);
            }
        }
        __syncthreads();   // protect sK/sV before next staging
    }

    // ---- epilogue ----
    float* og = out + qbase;
    #pragma unroll
    for (int u = 0; u < 2; u++) {
        const float i0 = 1.f / l[u][0];
        const float i1 = 1.f / l[u][1];
        #pragma unroll
        for (int nt = 0; nt < NNT; nt++) {
            float2 v0 = make_float2(o[u][nt][0] * i0, o[u][nt][1] * i0);
            float2 v1 = make_float2(o[u][nt][2] * i1, o[u][nt][3] * i1);
            *reinterpret_cast<float2*>(og + (r0 + 16 * u) * DIM + nt * 8 + 2 * tig)     = v0;
            *reinterpret_cast<float2*>(og + (r0 + 16 * u + 8) * DIM + nt * 8 + 2 * tig) = v1;
        }
    }
}

extern "C" void kernel_launch(void* const* d_in, const int* in_sizes, int n_in,
                              void* d_out, int out_size) {
    (void)in_sizes; (void)n_in; (void)out_size;
    const float* q = (const float*)d_in[0];
    const float* k = (const float*)d_in[1];
    const float* v = (const float*)d_in[2];
    float* out = (float*)d_out;

    // smem: max(Q staging 128*72*4, K 64*72*4 + V 64*72*2) = 36864 bytes
    const int smem_bytes = BR * PAD * 4;  // 36864
    cudaFuncSetAttribute(fa_tf32_kernel,
                         cudaFuncAttributeMaxDynamicSharedMemorySize, smem_bytes);

    dim3 grid(BATCH * HEADS, NQBLK);
    dim3 block(128);
    fa_tf32_kernel<<<grid, block, smem_bytes>>>(q, k, v, out);
}

// round 10
// speedup vs baseline: 2.4542x; 1.7390x over previous
#include <cuda_runtime.h>
#include <cuda_fp16.h>
#include <cstdint>
#include <math_constants.h>

// Causal attention B=4,H=16,S=2048,D=64 fp32. FA2, all-fp16 mma m16n8k16.
// Q/K/V staged fp16 in smem (72-half = 144B row stride, conflict-free for
// ldmatrix without any swizzle). Q/K fragments: ldmatrix.x4 non-trans;
// V: ldmatrix.x4.trans. P packed to fp16 A-fragments in registers (no smem
// round-trip). fp32 accumulate everywhere; online softmax in exp2 domain.

#define BATCH 4
#define HEADS 16
#define SEQ   2048
#define DIM   64

constexpr int BR  = 128;   // query rows per CTA (4 warps x 32)
constexpr int BC  = 64;    // key cols per tile
constexpr int PADH = 72;   // smem row stride in halves (144B)
constexpr int NQBLK = SEQ / BR;   // 16
constexpr int NNT = BC / 8;       // 8

__device__ __forceinline__ float ex2(float x) {
    float y;
    asm("ex2.approx.ftz.f32 %0, %1;" : "=f"(y) : "f"(x));
    return y;
}
__device__ __forceinline__ unsigned packh2(float a, float b) {
    __half2 h = __floats2half2_rn(a, b);
    return *reinterpret_cast<unsigned*>(&h);
}
__device__ __forceinline__ void mma_f16(float c[4],
                                        unsigned a0, unsigned a1, unsigned a2, unsigned a3,
                                        unsigned b0, unsigned b1) {
    asm volatile(
        "mma.sync.aligned.m16n8k16.row.col.f32.f16.f16.f32 "
        "{%0,%1,%2,%3}, {%4,%5,%6,%7}, {%8,%9}, {%0,%1,%2,%3};"
        : "+f"(c[0]), "+f"(c[1]), "+f"(c[2]), "+f"(c[3])
        : "r"(a0), "r"(a1), "r"(a2), "r"(a3), "r"(b0), "r"(b1));
}
__device__ __forceinline__ void ldsm4(unsigned r[4], unsigned saddr) {
    asm volatile(
        "ldmatrix.sync.aligned.m8n8.x4.shared.b16 {%0,%1,%2,%3}, [%4];"
        : "=r"(r[0]), "=r"(r[1]), "=r"(r[2]), "=r"(r[3]) : "r"(saddr));
}
__device__ __forceinline__ void ldsm4t(unsigned r[4], unsigned saddr) {
    asm volatile(
        "ldmatrix.sync.aligned.m8n8.x4.trans.shared.b16 {%0,%1,%2,%3}, [%4];"
        : "=r"(r[0]), "=r"(r[1]), "=r"(r[2]), "=r"(r[3]) : "r"(saddr));
}

__global__ void __launch_bounds__(128, 2)
fa_h16_kernel(const float* __restrict__ q,
              const float* __restrict__ k,
              const float* __restrict__ v,
              float* __restrict__ out) {
    extern __shared__ __half smh[];
    __half* sQh = smh;               // 128 x 72 halves (transient Q staging)
    __half* sKh = smh;               // 64 x 72 halves (reuses Q region)
    __half* sVh = smh + BC * PADH;   // 64 x 72 halves

    const int bh   = blockIdx.x;
    const int qblk = (NQBLK - 1) - blockIdx.y;   // heavy blocks first
    const int tid  = threadIdx.x;
    const int w    = tid >> 5;
    const int lane = tid & 31;
    const int g    = lane >> 2;
    const int tig  = lane & 3;
    const int r0   = w * 32 + g;

    const float QSCALE = 0.125f * 1.4426950408889634f;  // 1/sqrt(64)*log2(e)

    const size_t qbase  = ((size_t)bh * SEQ + (size_t)qblk * BR) * DIM;
    const size_t kvhead = (size_t)bh * SEQ * DIM;

    // ---- stage Q (scaled, fp16) ----
    #pragma unroll
    for (int i = 0; i < 16; i++) {
        int idx = i * 128 + tid;          // 2048 quads
        int row = idx >> 4;
        int c   = (idx & 15) << 2;        // half-index within row
        float4 qv = *reinterpret_cast<const float4*>(q + qbase + row * DIM + c);
        uint2 wv;
        wv.x = packh2(qv.x * QSCALE, qv.y * QSCALE);
        wv.y = packh2(qv.z * QSCALE, qv.w * QSCALE);
        *reinterpret_cast<uint2*>(sQh + row * PADH + c) = wv;
    }
    __syncthreads();

    // ---- Q fragments via ldmatrix.x4 (persist across KV loop) ----
    // tiles: a0=(m0-7,k0-7) a1=(m8-15,k0-7) a2=(m0-7,k8-15) a3=(m8-15,k8-15)
    const unsigned sq_base = (unsigned)__cvta_generic_to_shared(sQh);
    unsigned qa[2][4][4];
    {
        const int qrow = w * 32 + (lane & 15);       // lanes0-7:m0-7, 8-15:m8-15
        const int kun  = (lane >> 4);                // lanes16-31: k+8 unit
        #pragma unroll
        for (int u = 0; u < 2; u++)
            #pragma unroll
            for (int kt = 0; kt < 4; kt++) {
                unsigned addr = sq_base +
                    (unsigned)(((qrow + 16 * u) * PADH + (kt * 2 + kun) * 8) * 2);
                ldsm4(qa[u][kt], addr);
            }
    }
    __syncthreads();   // done with sQh; region becomes K

    float o[2][NNT][4];
    #pragma unroll
    for (int u = 0; u < 2; u++)
        #pragma unroll
        for (int nt = 0; nt < NNT; nt++) {
            o[u][nt][0] = 0.f; o[u][nt][1] = 0.f; o[u][nt][2] = 0.f; o[u][nt][3] = 0.f;
        }
    float m[2][2], l[2][2];
    m[0][0] = m[0][1] = m[1][0] = m[1][1] = -CUDART_INF_F;
    l[0][0] = l[0][1] = l[1][0] = l[1][1] = 0.f;

    const unsigned sk_base = (unsigned)__cvta_generic_to_shared(sKh);
    const unsigned sv_base = (unsigned)__cvta_generic_to_shared(sVh);

    // ldmatrix lane addressing (constant across loop)
    const int krow_lm = (lane & 7) + ((lane & 16) >> 1); // +8 for lanes16-31 (n-tile)
    const int ksel    = (lane >> 3) & 1;                 // k+8 unit for lanes 8-15,24-31
    const int vrow_lm = (lane & 7) + (lane & 8);         // +8 for lanes 8-15 (k-rows)
    const int vsel    = (lane >> 4);                     // n+8 unit for lanes16-31

    const int njb = 2 * qblk + 2;
    for (int jb = 0; jb < njb; jb++) {
        const float* kg = k + kvhead + (size_t)jb * BC * DIM;
        const float* vg = v + kvhead + (size_t)jb * BC * DIM;
        // ---- stage K and V (fp16, straight layout) ----
        #pragma unroll
        for (int i = 0; i < 8; i++) {
            int idx = i * 128 + tid;          // 1024 quads
            int row = idx >> 4;
            int c   = (idx & 15) << 2;
            float4 k4 = *reinterpret_cast<const float4*>(kg + row * DIM + c);
            uint2 wk;
            wk.x = packh2(k4.x, k4.y);
            wk.y = packh2(k4.z, k4.w);
            *reinterpret_cast<uint2*>(sKh + row * PADH + c) = wk;
            float4 v4 = *reinterpret_cast<const float4*>(vg + row * DIM + c);
            uint2 wvv;
            wvv.x = packh2(v4.x, v4.y);
            wvv.y = packh2(v4.z, v4.w);
            *reinterpret_cast<uint2*>(sVh + row * PADH + c) = wvv;
        }
        __syncthreads();

        // ---- S = Q K^T (fp16 k16) ----
        float s[2][NNT][4];
        #pragma unroll
        for (int u = 0; u < 2; u++)
            #pragma unroll
            for (int nt = 0; nt < NNT; nt++) {
                s[u][nt][0] = 0.f; s[u][nt][1] = 0.f; s[u][nt][2] = 0.f; s[u][nt][3] = 0.f;
            }
        #pragma unroll
        for (int kt = 0; kt < 4; kt++) {
            #pragma unroll
            for (int nb = 0; nb < 4; nb++) {
                // tiles: (n0-7,k0) (n0-7,k8) (n8-15,k0) (n8-15,k8)
                unsigned addr = sk_base +
                    (unsigned)(((nb * 16 + krow_lm) * PADH + (kt * 2 + ksel) * 8) * 2);
                unsigned kb[4];
                ldsm4(kb, addr);
                mma_f16(s[0][2 * nb],     qa[0][kt][0], qa[0][kt][1], qa[0][kt][2], qa[0][kt][3], kb[0], kb[1]);
                mma_f16(s[0][2 * nb + 1], qa[0][kt][0], qa[0][kt][1], qa[0][kt][2], qa[0][kt][3], kb[2], kb[3]);
                mma_f16(s[1][2 * nb],     qa[1][kt][0], qa[1][kt][1], qa[1][kt][2], qa[1][kt][3], kb[0], kb[1]);
                mma_f16(s[1][2 * nb + 1], qa[1][kt][0], qa[1][kt][1], qa[1][kt][2], qa[1][kt][3], kb[2], kb[3]);
            }
        }

        // ---- causal mask (diagonal-straddling blocks only) ----
        if (jb >= 2 * qblk) {
            const int colb = jb * BC;
            #pragma unroll
            for (int u = 0; u < 2; u++) {
                const int rowg = qblk * BR + r0 + 16 * u;
                #pragma unroll
                for (int nt = 0; nt < NNT; nt++) {
                    int c0 = colb + nt * 8 + 2 * tig;
                    int c1 = c0 + 1;
                    if (c0 > rowg)     s[u][nt][0] = -CUDART_INF_F;
                    if (c1 > rowg)     s[u][nt][1] = -CUDART_INF_F;
                    if (c0 > rowg + 8) s[u][nt][2] = -CUDART_INF_F;
                    if (c1 > rowg + 8) s[u][nt][3] = -CUDART_INF_F;
                }
            }
        }

        // ---- online softmax; pack P into fp16 A-fragments (registers) ----
        unsigned pa[2][4][4];
        #pragma unroll
        for (int u = 0; u < 2; u++) {
            float mx0 = -CUDART_INF_F, mx1 = -CUDART_INF_F;
            #pragma unroll
            for (int nt = 0; nt < NNT; nt++) {
                mx0 = fmaxf(mx0, fmaxf(s[u][nt][0], s[u][nt][1]));
                mx1 = fmaxf(mx1, fmaxf(s[u][nt][2], s[u][nt][3]));
            }
            mx0 = fmaxf(mx0, __shfl_xor_sync(0xffffffffu, mx0, 1));
            mx0 = fmaxf(mx0, __shfl_xor_sync(0xffffffffu, mx0, 2));
            mx1 = fmaxf(mx1, __shfl_xor_sync(0xffffffffu, mx1, 1));
            mx1 = fmaxf(mx1, __shfl_xor_sync(0xffffffffu, mx1, 2));

            float mn0 = fmaxf(m[u][0], mx0);
            float mn1 = fmaxf(m[u][1], mx1);
            float a0 = ex2(m[u][0] - mn0);
            float a1 = ex2(m[u][1] - mn1);
            m[u][0] = mn0; m[u][1] = mn1;

            float rs0 = 0.f, rs1 = 0.f;
            #pragma unroll
            for (int nt = 0; nt < NNT; nt++) {
                s[u][nt][0] = ex2(s[u][nt][0] - mn0);
                s[u][nt][1] = ex2(s[u][nt][1] - mn0);
                s[u][nt][2] = ex2(s[u][nt][2] - mn1);
                s[u][nt][3] = ex2(s[u][nt][3] - mn1);
                rs0 += s[u][nt][0] + s[u][nt][1];
                rs1 += s[u][nt][2] + s[u][nt][3];
            }
            rs0 += __shfl_xor_sync(0xffffffffu, rs0, 1);
            rs0 += __shfl_xor_sync(0xffffffffu, rs0, 2);
            rs1 += __shfl_xor_sync(0xffffffffu, rs1, 1);
            rs1 += __shfl_xor_sync(0xffffffffu, rs1, 2);
            l[u][0] = l[u][0] * a0 + rs0;
            l[u][1] = l[u][1] * a1 + rs1;

            #pragma unroll
            for (int nt = 0; nt < NNT; nt++) {
                o[u][nt][0] *= a0; o[u][nt][1] *= a0;
                o[u][nt][2] *= a1; o[u][nt][3] *= a1;
            }

            // pack P: A-fragment layout matches S accumulator layout exactly
            #pragma unroll
            for (int t = 0; t < 4; t++) {
                pa[u][t][0] = packh2(s[u][2*t][0],   s[u][2*t][1]);
                pa[u][t][1] = packh2(s[u][2*t][2],   s[u][2*t][3]);
                pa[u][t][2] = packh2(s[u][2*t+1][0], s[u][2*t+1][1]);
                pa[u][t][3] = packh2(s[u][2*t+1][2], s[u][2*t+1][3]);
            }
        }

        // ---- O += P V (fp16 k16, V via ldmatrix.x4.trans) ----
        #pragma unroll
        for (int kt = 0; kt < 4; kt++) {
            #pragma unroll
            for (int nb = 0; nb < 4; nb++) {
                // tiles: (k0-7,n0) (k8-15,n0) (k0-7,n8) (k8-15,n8)
                unsigned addr = sv_base +
                    (unsigned)(((kt * 16 + vrow_lm) * PADH + (nb * 2 + vsel) * 8) * 2);
                unsigned vb[4];
                ldsm4t(vb, addr);
                mma_f16(o[0][2 * nb],     pa[0][kt][0], pa[0][kt][1], pa[0][kt][2], pa[0][kt][3], vb[0], vb[1]);
                mma_f16(o[0][2 * nb + 1], pa[0][kt][0], pa[0][kt][1], pa[0][kt][2], pa[0][kt][3], vb[2], vb[3]);
                mma_f16(o[1][2 * nb],     pa[1][kt][0], pa[1][kt][1], pa[1][kt][2], pa[1][kt][3], vb[0], vb[1]);
                mma_f16(o[1][2 * nb + 1], pa[1][kt][0], pa[1][kt][1], pa[1][kt][2], pa[1][kt][3], vb[2], vb[3]);
            }
        }
        __syncthreads();   // protect sKh/sVh before next staging
    }

    // ---- epilogue ----
    float* og = out + qbase;
    #pragma unroll
    for (int u = 0; u < 2; u++) {
        const float i0 = 1.f / l[u][0];
        const float i1 = 1.f / l[u][1];
        #pragma unroll
        for (int nt = 0; nt < NNT; nt++) {
            float2 v0 = make_float2(o[u][nt][0] * i0, o[u][nt][1] * i0);
            float2 v1 = make_float2(o[u][nt][2] * i1, o[u][nt][3] * i1);
            *reinterpret_cast<float2*>(og + (r0 + 16 * u) * DIM + nt * 8 + 2 * tig)     = v0;
            *reinterpret_cast<float2*>(og + (r0 + 16 * u + 8) * DIM + nt * 8 + 2 * tig) = v1;
        }
    }
}

extern "C" void kernel_launch(void* const* d_in, const int* in_sizes, int n_in,
                              void* d_out, int out_size) {
    (void)in_sizes; (void)n_in; (void)out_size;
    const float* q = (const float*)d_in[0];
    const float* k = (const float*)d_in[1];
    const float* v = (const float*)d_in[2];
    float* out = (float*)d_out;

    // smem: max(Q staging 128*72, K 64*72 + V 64*72) halves = 18432 bytes
    const int smem_bytes = BR * PADH * 2;  // 18432
    cudaFuncSetAttribute(fa_h16_kernel,
                         cudaFuncAttributeMaxDynamicSharedMemorySize, smem_bytes);

    dim3 grid(BATCH * HEADS, NQBLK);
    dim3 block(128);
    fa_h16_kernel<<<grid, block, smem_bytes>>>(q, k, v, out);
}